// round 16
// baseline (speedup 1.0000x reference)
#include <cuda_runtime.h>
#include <cuda_bf16.h>
#include <cuda_fp16.h>
#include <math.h>
#include <stdint.h>

// ---------------- problem constants ----------------
#define BB     4
#define SEQ    2048
#define DIMX   768
#define HEADS  8
#define HD     64
#define INNER  512
#define FFN    3072
#define ROWS   (BB*SEQ)      // 8192

// ---------------- scratch (device globals) ----------------
__device__ float g_x1[ROWS*DIMX];

__device__ __half g_nx16[ROWS*DIMX];
__device__ __half g_nc16[ROWS*DIMX];
__device__ __half g_h16 [ROWS*DIMX];
__device__ __half g_ao16[ROWS*INNER];
__device__ __half g_ge16[ROWS*FFN];

__device__ __half g_q16[ROWS*INNER];
__device__ __half g_k16[ROWS*INNER];
__device__ __half g_v16[ROWS*INNER];

__device__ __half g_wq16[INNER*DIMX];
__device__ __half g_wk16[INNER*DIMX];
__device__ __half g_wv16[INNER*DIMX];
__device__ __half g_wo16[DIMX*INNER];
__device__ __half g_w116[FFN*DIMX];
__device__ __half g_w216[DIMX*FFN];

// ---------------- PTX helpers (base-target safe: sm_80+) ----------------
__device__ __forceinline__ uint32_t smem_u32(const void* p)
{
    return (uint32_t)__cvta_generic_to_shared(p);
}
__device__ __forceinline__ void cp16(uint32_t dst, const void* src)
{
    asm volatile("cp.async.cg.shared.global [%0], [%1], 16;\n" :: "r"(dst), "l"(src));
}
__device__ __forceinline__ void cp_commit()
{
    asm volatile("cp.async.commit_group;\n" ::: "memory");
}
template <int N>
__device__ __forceinline__ void cp_wait()
{
    asm volatile("cp.async.wait_group %0;\n" :: "n"(N) : "memory");
}
__device__ __forceinline__ void ldsm4(uint32_t* r, uint32_t addr)
{
    asm volatile("ldmatrix.sync.aligned.m8n8.x4.shared.b16 {%0,%1,%2,%3}, [%4];"
                 : "=r"(r[0]), "=r"(r[1]), "=r"(r[2]), "=r"(r[3]) : "r"(addr));
}
__device__ __forceinline__ void ldsm4t(uint32_t* r, uint32_t addr)
{
    asm volatile("ldmatrix.sync.aligned.m8n8.x4.trans.shared.b16 {%0,%1,%2,%3}, [%4];"
                 : "=r"(r[0]), "=r"(r[1]), "=r"(r[2]), "=r"(r[3]) : "r"(addr));
}
__device__ __forceinline__ void mma16816h(float* d, const uint32_t* a, const uint32_t* b)
{
    asm volatile("mma.sync.aligned.m16n8k16.row.col.f32.f16.f16.f32 "
                 "{%0,%1,%2,%3}, {%4,%5,%6,%7}, {%8,%9}, {%0,%1,%2,%3};\n"
                 : "+f"(d[0]), "+f"(d[1]), "+f"(d[2]), "+f"(d[3])
                 : "r"(a[0]), "r"(a[1]), "r"(a[2]), "r"(a[3]), "r"(b[0]), "r"(b[1]));
}
__device__ __forceinline__ float ex2(float x)
{
    float y;
    asm("ex2.approx.f32 %0, %1;" : "=f"(y) : "f"(x));
    return y;
}
__device__ __forceinline__ uint32_t pack_h2(float a, float b)
{
    __half2 t = __floats2half2_rn(a, b);
    return *(uint32_t*)&t;
}

// ---------------- LayerNorm -> fp16 ----------------
__device__ __forceinline__ void ln_body(const float* __restrict__ in,
                                        const float* __restrict__ gamma,
                                        const float* __restrict__ beta,
                                        __half* __restrict__ o16,
                                        int row)
{
    const int t = threadIdx.x;
    const float* p = in + (size_t)row * DIMX;

    float v0 = p[t], v1 = p[t + 256], v2 = p[t + 512];
    float s  = v0 + v1 + v2;
    float s2 = v0*v0 + v1*v1 + v2*v2;
    #pragma unroll
    for (int o = 16; o > 0; o >>= 1) {
        s  += __shfl_xor_sync(0xFFFFFFFFu, s,  o);
        s2 += __shfl_xor_sync(0xFFFFFFFFu, s2, o);
    }
    __shared__ float ws[8], ws2[8];
    const int w = t >> 5, ln = t & 31;
    if (ln == 0) { ws[w] = s; ws2[w] = s2; }
    __syncthreads();
    s = 0.f; s2 = 0.f;
    #pragma unroll
    for (int i = 0; i < 8; i++) { s += ws[i]; s2 += ws2[i]; }

    const float mu  = s  * (1.f / DIMX);
    const float var = s2 * (1.f / DIMX) - mu * mu;
    const float inv = rsqrtf(var + 1e-5f);

    const size_t base = (size_t)row * DIMX;
    #pragma unroll
    for (int i = 0; i < 3; i++) {
        const int c = t + i * 256;
        const float vv = (i == 0 ? v0 : i == 1 ? v1 : v2);
        const float y = (vv - mu) * inv * gamma[c] + beta[c];
        o16[base + c] = __float2half_rn(y);
    }
}

__global__ void __launch_bounds__(256) ln16_kernel(const float* __restrict__ in,
                                                   const float* __restrict__ gamma,
                                                   const float* __restrict__ beta,
                                                   __half* __restrict__ o16)
{
    ln_body(in, gamma, beta, o16, blockIdx.x);
}

__global__ void __launch_bounds__(256) ln_dual_kernel(const float* __restrict__ x,
                                                      const float* __restrict__ ctx,
                                                      const float* __restrict__ gamma,
                                                      const float* __restrict__ beta,
                                                      __half* __restrict__ x16,
                                                      __half* __restrict__ c16)
{
    const int r = blockIdx.x;
    if (r < ROWS) ln_body(x, gamma, beta, x16, r);
    else          ln_body(ctx, gamma, beta, c16, r - ROWS);
}

// ---------------- fused weight transpose + fp16 convert (all 6, 1 launch) ----------------
__device__ __forceinline__ void wconv_body(const float* __restrict__ W,
                                           __half* __restrict__ T16,
                                           int K, int N, int bx, int by)
{
    __shared__ float tile[32][33];
    const int n0 = bx * 32, k0 = by * 32;
    const int tx = threadIdx.x, ty = threadIdx.y;   // 32 x 8
    #pragma unroll
    for (int i = 0; i < 4; i++)
        tile[ty + 8 * i][tx] = W[(size_t)(k0 + ty + 8 * i) * N + n0 + tx];
    __syncthreads();
    #pragma unroll
    for (int i = 0; i < 4; i++) {
        const float v = tile[tx][ty + 8 * i];
        const size_t idx = (size_t)(n0 + ty + 8 * i) * K + k0 + tx;
        T16[idx] = __float2half_rn(v);
    }
}

#define WC_BLOCKS 6144
__global__ void __launch_bounds__(256) wconv_all(const float* Wq, const float* Wk, const float* Wv,
                                                 const float* Wo, const float* W1, const float* W2,
                                                 __half* wq16, __half* wk16, __half* wv16,
                                                 __half* wo16, __half* w116, __half* w216)
{
    const int id = blockIdx.x;
    if (id < 384) {
        wconv_body(Wq, wq16, DIMX, INNER, id % 16, id / 16);
    } else if (id < 768) {
        const int l = id - 384;
        wconv_body(Wk, wk16, DIMX, INNER, l % 16, l / 16);
    } else if (id < 1152) {
        const int l = id - 768;
        wconv_body(Wv, wv16, DIMX, INNER, l % 16, l / 16);
    } else if (id < 1536) {
        const int l = id - 1152;
        wconv_body(Wo, wo16, INNER, DIMX, l % 24, l / 24);
    } else if (id < 3840) {
        const int l = id - 1536;
        wconv_body(W1, w116, DIMX, FFN, l % 96, l / 96);
    } else {
        const int l = id - 3840;
        wconv_body(W2, w216, FFN, DIMX, l % 24, l / 24);
    }
}

// ---------------- fp16 1-pass HMMA GEMM, 128x128 tile, 3-stage pipeline ----------------
// MODE 2: C16 = fp16(gelu(D + bias))
// MODE 4: C16 = fp16(D * oscale)
#define HG_STRIDE 40
#define HG_B (128 * HG_STRIDE)                     // elem offset of B region
#define HG_STAGE_BYTES (2 * 128 * HG_STRIDE * 2)   // 20480
#define HG_SMEM (3 * HG_STAGE_BYTES)               // 61440

template <int MODE>
__device__ __forceinline__ void hgemm_body(const __half* __restrict__ A,
                                           const __half* __restrict__ B,
                                           const float* __restrict__ bias,
                                           float* __restrict__ Cf,
                                           __half* __restrict__ C16,
                                           int N, int K, float oscale,
                                           int bx, int by)
{
    extern __shared__ char dsm[];
    const uint32_t sb = smem_u32(dsm);

    const int t    = threadIdx.x;
    const int lane = t & 31;
    const int wid  = t >> 5;
    const int wm   = wid >> 2;
    const int wn   = wid & 3;

    const int row0 = by * 128;
    const int col0 = bx * 128;
    const int NC = K >> 5;              // chunks of 32

    const int grow = t >> 1;
    const int ghalf = t & 1;
    const uint32_t sm_off = (uint32_t)(grow * HG_STRIDE) * 2 + (uint32_t)ghalf * 32;

    const int a_row = wm * 64 + (lane & 7) + ((lane >> 3) & 1) * 8;
    const int a_col = (lane >> 4) * 8;
    const int b_row = wn * 32 + (lane & 7) + (lane >> 4) * 8;
    const int b_col = ((lane >> 3) & 1) * 8;

    float acc[4][4][4];
    #pragma unroll
    for (int mt = 0; mt < 4; mt++)
        #pragma unroll
        for (int nt = 0; nt < 4; nt++)
            #pragma unroll
            for (int rr = 0; rr < 4; rr++) acc[mt][nt][rr] = 0.f;

    // prologue: issue chunks 0 and 1 as separate groups
    #pragma unroll
    for (int pc = 0; pc < 2; pc++) {
        const uint32_t sp = sb + (uint32_t)pc * HG_STAGE_BYTES;
        const size_t ga = (size_t)(row0 + grow) * K + pc * 32 + ghalf * 16;
        const size_t gb = (size_t)(col0 + grow) * K + pc * 32 + ghalf * 16;
        cp16(sp + sm_off,                  A + ga);
        cp16(sp + sm_off + 16,             A + ga + 8);
        cp16(sp + 2*HG_B + sm_off,         B + gb);
        cp16(sp + 2*HG_B + sm_off + 16,    B + gb + 8);
        cp_commit();
    }

    for (int c = 0; c < NC; c++) {
        const uint32_t st = sb + (uint32_t)(c % 3) * HG_STAGE_BYTES;

        cp_wait<1>();        // chunk c landed (chunk c+1 may be in flight)
        __syncthreads();

        if (c + 2 < NC) {
            const uint32_t sn = sb + (uint32_t)((c + 2) % 3) * HG_STAGE_BYTES;
            const size_t ga = (size_t)(row0 + grow) * K + (c + 2) * 32 + ghalf * 16;
            const size_t gb = (size_t)(col0 + grow) * K + (c + 2) * 32 + ghalf * 16;
            cp16(sn + sm_off,               A + ga);
            cp16(sn + sm_off + 16,          A + ga + 8);
            cp16(sn + 2*HG_B + sm_off,      B + gb);
            cp16(sn + 2*HG_B + sm_off + 16, B + gb + 8);
        }
        cp_commit();         // unconditional: keeps group count exact

        #pragma unroll
        for (int ks = 0; ks < 2; ks++) {
            uint32_t a[4][4], b[4][2];
            #pragma unroll
            for (int mt = 0; mt < 4; mt++) {
                const uint32_t ea = st + 2u * (uint32_t)((a_row + mt * 16) * HG_STRIDE + a_col + ks * 16);
                ldsm4(a[mt], ea);
            }
            #pragma unroll
            for (int p = 0; p < 2; p++) {
                const uint32_t eb = st + 2u * (uint32_t)(HG_B + (b_row + p * 16) * HG_STRIDE + b_col + ks * 16);
                uint32_t r[4];
                ldsm4(r, eb);
                b[2*p][0] = r[0]; b[2*p][1] = r[1]; b[2*p+1][0] = r[2]; b[2*p+1][1] = r[3];
            }
            #pragma unroll
            for (int mt = 0; mt < 4; mt++)
                #pragma unroll
                for (int nt = 0; nt < 4; nt++)
                    mma16816h(acc[mt][nt], a[mt], b[nt]);
        }
    }

    const int gid = lane >> 2, tig = lane & 3;
    #pragma unroll
    for (int mt = 0; mt < 4; mt++) {
        #pragma unroll
        for (int nt = 0; nt < 4; nt++) {
            const int col = col0 + wn * 32 + nt * 8 + tig * 2;
            #pragma unroll
            for (int half = 0; half < 2; half++) {
                const int row = row0 + wm * 64 + mt * 16 + gid + half * 8;
                const size_t idx = (size_t)row * N + col;
                float o0 = acc[mt][nt][half * 2 + 0];
                float o1 = acc[mt][nt][half * 2 + 1];
                if (MODE == 2) {
                    const float2 b2 = *(const float2*)(bias + col);
                    const float v0 = o0 + b2.x;
                    const float v1 = o1 + b2.y;
                    const float gl0 = 0.5f * v0 * (1.0f + erff(v0 * 0.70710678118654752f));
                    const float gl1 = 0.5f * v1 * (1.0f + erff(v1 * 0.70710678118654752f));
                    *(__half2*)(C16 + idx) = __floats2half2_rn(gl0, gl1);
                } else {
                    *(__half2*)(C16 + idx) = __floats2half2_rn(o0 * oscale, o1 * oscale);
                }
            }
        }
    }
}

template <int MODE>
__global__ void __launch_bounds__(256, 2) hgemm(const __half* __restrict__ A,
                                                const __half* __restrict__ B,
                                                const float* __restrict__ bias,
                                                float* __restrict__ Cf,
                                                __half* __restrict__ C16,
                                                int N, int K, float oscale)
{
    hgemm_body<MODE>(A, B, bias, Cf, C16, N, K, oscale, blockIdx.x, blockIdx.y);
}

// fused QKV -> fp16: z=0 Q (A=nx, scaled by 0.125*log2e), z=1 K, z=2 V (A=nc)
__global__ void __launch_bounds__(256, 2) qkv_gemm(const __half* nx16, const __half* nc16,
                                                   const __half* wq16, const __half* wk16,
                                                   const __half* wv16,
                                                   __half* q16, __half* k16, __half* v16)
{
    const int z = blockIdx.z;
    const __half* A = (z == 0) ? nx16 : nc16;
    const __half* B = (z == 0) ? wq16 : (z == 1) ? wk16 : wv16;
    __half* C = (z == 0) ? q16 : (z == 1) ? k16 : v16;
    const float osc = (z == 0) ? (0.125f * 1.44269504f) : 1.0f;
    hgemm_body<4>(A, B, nullptr, nullptr, C, INNER, DIMX, osc, blockIdx.x, blockIdx.y);
}

// ---------------- fp16 GEMM, 64x128 tile (wave-friendly N=768 GEMMs), 3-stage ----------------
// C = D + bias + res (fp32 out). Grid: (N/128, M/64).
#define H64_STRIDE 40
#define H64_A_ELEMS (64 * H64_STRIDE)              // 2560
#define H64_STAGE_ELEMS ((64 + 128) * H64_STRIDE)  // 7680
#define H64_STAGE_BYTES (H64_STAGE_ELEMS * 2)      // 15360
#define H64_SMEM (3 * H64_STAGE_BYTES)             // 46080

__global__ void __launch_bounds__(256, 2) hgemm64(const __half* __restrict__ A,
                                                  const __half* __restrict__ B,
                                                  const float* __restrict__ bias,
                                                  const float* __restrict__ res,
                                                  float* __restrict__ Cf,
                                                  int N, int K)
{
    extern __shared__ char dsm[];
    const uint32_t sb = smem_u32(dsm);

    const int t    = threadIdx.x;
    const int lane = t & 31;
    const int wid  = t >> 5;
    const int wm   = wid >> 2;          // 0..1 (32-row slab)
    const int wn   = wid & 3;           // 0..3 (32-col slab)

    const int row0 = blockIdx.y * 64;
    const int col0 = blockIdx.x * 128;
    const int NC = K >> 5;

    const int grow = t >> 1;            // 0..127
    const int ghalf = t & 1;
    const uint32_t smA = (uint32_t)(grow * H64_STRIDE) * 2 + (uint32_t)ghalf * 32;           // valid for t<128
    const uint32_t smB = (uint32_t)((H64_A_ELEMS + grow * H64_STRIDE)) * 2 + (uint32_t)ghalf * 32;

    const int a_row = wm * 32 + (lane & 7) + ((lane >> 3) & 1) * 8;
    const int a_col = (lane >> 4) * 8;
    const int b_row = wn * 32 + (lane & 7) + (lane >> 4) * 8;
    const int b_col = ((lane >> 3) & 1) * 8;

    float acc[2][4][4];
    #pragma unroll
    for (int mt = 0; mt < 2; mt++)
        #pragma unroll
        for (int nt = 0; nt < 4; nt++)
            #pragma unroll
            for (int rr = 0; rr < 4; rr++) acc[mt][nt][rr] = 0.f;

    // prologue: chunks 0 and 1
    #pragma unroll
    for (int pc = 0; pc < 2; pc++) {
        const uint32_t sp = sb + (uint32_t)pc * H64_STAGE_BYTES;
        if (t < 128) {
            const size_t ga = (size_t)(row0 + grow) * K + pc * 32 + ghalf * 16;
            cp16(sp + smA,      A + ga);
            cp16(sp + smA + 16, A + ga + 8);
        }
        const size_t gb = (size_t)(col0 + grow) * K + pc * 32 + ghalf * 16;
        cp16(sp + smB,      B + gb);
        cp16(sp + smB + 16, B + gb + 8);
        cp_commit();
    }

    for (int c = 0; c < NC; c++) {
        const uint32_t st = sb + (uint32_t)(c % 3) * H64_STAGE_BYTES;

        cp_wait<1>();
        __syncthreads();

        if (c + 2 < NC) {
            const uint32_t sn = sb + (uint32_t)((c + 2) % 3) * H64_STAGE_BYTES;
            if (t < 128) {
                const size_t ga = (size_t)(row0 + grow) * K + (c + 2) * 32 + ghalf * 16;
                cp16(sn + smA,      A + ga);
                cp16(sn + smA + 16, A + ga + 8);
            }
            const size_t gb = (size_t)(col0 + grow) * K + (c + 2) * 32 + ghalf * 16;
            cp16(sn + smB,      B + gb);
            cp16(sn + smB + 16, B + gb + 8);
        }
        cp_commit();

        #pragma unroll
        for (int ks = 0; ks < 2; ks++) {
            uint32_t a[2][4], b[4][2];
            #pragma unroll
            for (int mt = 0; mt < 2; mt++) {
                const uint32_t ea = st + 2u * (uint32_t)((a_row + mt * 16) * H64_STRIDE + a_col + ks * 16);
                ldsm4(a[mt], ea);
            }
            #pragma unroll
            for (int p = 0; p < 2; p++) {
                const uint32_t eb = st + 2u * (uint32_t)(H64_A_ELEMS + (b_row + p * 16) * H64_STRIDE + b_col + ks * 16);
                uint32_t r[4];
                ldsm4(r, eb);
                b[2*p][0] = r[0]; b[2*p][1] = r[1]; b[2*p+1][0] = r[2]; b[2*p+1][1] = r[3];
            }
            #pragma unroll
            for (int mt = 0; mt < 2; mt++)
                #pragma unroll
                for (int nt = 0; nt < 4; nt++)
                    mma16816h(acc[mt][nt], a[mt], b[nt]);
        }
    }

    const int gid = lane >> 2, tig = lane & 3;
    #pragma unroll
    for (int mt = 0; mt < 2; mt++) {
        #pragma unroll
        for (int nt = 0; nt < 4; nt++) {
            const int col = col0 + wn * 32 + nt * 8 + tig * 2;
            #pragma unroll
            for (int half = 0; half < 2; half++) {
                const int row = row0 + wm * 32 + mt * 16 + gid + half * 8;
                const size_t idx = (size_t)row * N + col;
                const float2 b2 = *(const float2*)(bias + col);
                const float2 r2 = *(const float2*)(res + idx);
                float2 w2;
                w2.x = acc[mt][nt][half * 2 + 0] + b2.x + r2.x;
                w2.y = acc[mt][nt][half * 2 + 1] + b2.y + r2.y;
                *(float2*)(Cf + idx) = w2;
            }
        }
    }
}

// ---------------- fp16 HMMA flash attention (1-pass, no-max softmax, 3-stage) ----------------
// CTA: 128 q-rows x head (dim 64). 8 warps, each m16. K/V chunks of 64 keys.
#define KST 72
#define KTILE_B (64 * KST * 2)      // 9216
#define STAGE_B (2 * KTILE_B)       // 18432: K,V
#define FA_SMEM (3 * STAGE_B)       // 55296

__device__ __forceinline__ void fa_load_chunk(uint32_t st, int arr, int rr, int hf,
                                              const __half* kb, const __half* vb, int m0)
{
    const __half* gb = arr ? vb : kb;
    const uint32_t dst = st + (uint32_t)arr * KTILE_B + (uint32_t)(rr * KST + hf * 32) * 2;
    const __half* src = gb + (size_t)(m0 + rr) * INNER + hf * 32;
    #pragma unroll
    for (int j = 0; j < 4; j++)
        cp16(dst + j * 16, src + j * 8);
}

__global__ void __launch_bounds__(256, 2) fa_kernel(const __half* __restrict__ q16,
                                                    const __half* __restrict__ k16,
                                                    const __half* __restrict__ v16,
                                                    __half* __restrict__ ao16)
{
    extern __shared__ char fsm[];
    const uint32_t sb = smem_u32(fsm);

    const int n0 = blockIdx.x * 128;
    const int h  = blockIdx.y;
    const int b  = blockIdx.z;
    const int t  = threadIdx.x;
    const int lane = t & 31;
    const int w  = t >> 5;
    const int gid = lane >> 2, tig = lane & 3;

    // ---- stage Q (128 x 64 fp16) into stage-0 region, ldmatrix to regs ----
    {
        const int qrow = t >> 1, qhf = t & 1;
        const __half* qb = q16 + (size_t)(b * SEQ + n0 + qrow) * INNER + h * HD + qhf * 32;
        const uint32_t dst = sb + (uint32_t)(qrow * KST + qhf * 32) * 2;
        #pragma unroll
        for (int j = 0; j < 4; j++)
            cp16(dst + j * 16, qb + j * 8);
        cp_commit();
        cp_wait<0>();
        __syncthreads();
    }

    uint32_t qf[4][4];
    {
        const int a_row = w * 16 + (lane & 7) + ((lane >> 3) & 1) * 8;
        const int a_col = (lane >> 4) * 8;
        #pragma unroll
        for (int kt = 0; kt < 4; kt++) {
            const uint32_t ea = sb + 2u * (uint32_t)(a_row * KST + kt * 16 + a_col);
            ldsm4(qf[kt], ea);
        }
    }
    __syncthreads();   // everyone done reading Q staging before K/V overwrite

    float lr0 = 0.f, lr1 = 0.f;
    float o[8][4];
    #pragma unroll
    for (int nt = 0; nt < 8; nt++)
        #pragma unroll
        for (int rr = 0; rr < 4; rr++) o[nt][rr] = 0.f;

    const __half* kbase = k16 + (size_t)(b * SEQ) * INNER + h * HD;
    const __half* vbase = v16 + (size_t)(b * SEQ) * INNER + h * HD;

    const int arr = t >> 7;
    const int rem = t & 127;
    const int rr_ = rem >> 1;
    const int hf_ = rem & 1;

    const int kb_row = (lane & 7) + (lane >> 4) * 8;       // K as B (non-trans)
    const int kb_col = ((lane >> 3) & 1) * 8;
    const int v_row  = (lane & 7) + ((lane >> 3) & 1) * 8; // V via trans
    const int v_cb   = (lane >> 4) * 8;

    // prologue: issue chunks 0 and 1 as separate groups
    fa_load_chunk(sb,           arr, rr_, hf_, kbase, vbase, 0);
    cp_commit();
    fa_load_chunk(sb + STAGE_B, arr, rr_, hf_, kbase, vbase, 64);
    cp_commit();

    const int NCH = SEQ / 64;
    for (int c = 0; c < NCH; c++) {
        const uint32_t st = sb + (uint32_t)(c % 3) * STAGE_B;

        cp_wait<1>();      // chunk c landed; chunk c+1 may still fly
        __syncthreads();

        if (c + 2 < NCH) {
            fa_load_chunk(sb + (uint32_t)((c + 2) % 3) * STAGE_B, arr, rr_, hf_,
                          kbase, vbase, (c + 2) * 64);
        }
        cp_commit();       // unconditional: keeps group count exact

        // ---- S = Q K^T; scores include scale*log2(e) ----
        float s[8][4];
        #pragma unroll
        for (int nt = 0; nt < 8; nt++)
            #pragma unroll
            for (int rr = 0; rr < 4; rr++) s[nt][rr] = 0.f;

        #pragma unroll
        for (int kt = 0; kt < 4; kt++) {
            #pragma unroll
            for (int p = 0; p < 4; p++) {
                const uint32_t eb = st + 2u * (uint32_t)((p * 16 + kb_row) * KST + kt * 16 + kb_col);
                uint32_t r[4];
                ldsm4(r, eb);
                mma16816h(s[2*p],   qf[kt], r);
                mma16816h(s[2*p+1], qf[kt], r + 2);
            }
        }

        // ---- no-max softmax: P = 2^s ----
        uint32_t pa[4][4];
        #pragma unroll
        for (int nt = 0; nt < 8; nt++) {
            const float p0 = ex2(s[nt][0]);
            const float p1 = ex2(s[nt][1]);
            const float p2 = ex2(s[nt][2]);
            const float p3 = ex2(s[nt][3]);
            lr0 += p0 + p1;
            lr1 += p2 + p3;
            const int kt = nt >> 1, hf = nt & 1;
            pa[kt][hf * 2 + 0] = pack_h2(p0, p1);
            pa[kt][hf * 2 + 1] = pack_h2(p2, p3);
        }

        // ---- O += P V, V via ldmatrix.trans ----
        #pragma unroll
        for (int kt = 0; kt < 4; kt++) {
            #pragma unroll
            for (int g = 0; g < 4; g++) {
                const uint32_t ev = st + (uint32_t)KTILE_B
                                  + 2u * (uint32_t)((kt * 16 + v_row) * KST + g * 16 + v_cb);
                uint32_t r[4];
                ldsm4t(r, ev);
                mma16816h(o[2*g],   pa[kt], r);
                mma16816h(o[2*g+1], pa[kt], r + 2);
            }
        }
    }

    // ---- deferred row-sum reduction + epilogue -> fp16 ----
    lr0 += __shfl_xor_sync(0xFFFFFFFFu, lr0, 1);
    lr0 += __shfl_xor_sync(0xFFFFFFFFu, lr0, 2);
    lr1 += __shfl_xor_sync(0xFFFFFFFFu, lr1, 1);
    lr1 += __shfl_xor_sync(0xFFFFFFFFu, lr1, 2);
    const float inv0 = 1.f / lr0;
    const float inv1 = 1.f / lr1;
    #pragma unroll
    for (int nt = 0; nt < 8; nt++) {
        const int col = h * HD + nt * 8 + tig * 2;
        #pragma unroll
        for (int half = 0; half < 2; half++) {
            const int row = n0 + w * 16 + gid + half * 8;
            const size_t idx = (size_t)(b * SEQ + row) * INNER + col;
            const float inv = half ? inv1 : inv0;
            *(__half2*)(ao16 + idx) = __floats2half2_rn(o[nt][half * 2 + 0] * inv,
                                                        o[nt][half * 2 + 1] * inv);
        }
    }
}

// ---------------- host launcher ----------------
static float* sym(const void* s)
{
    void* p = nullptr;
    cudaGetSymbolAddress(&p, s);
    return (float*)p;
}

extern "C" void kernel_launch(void* const* d_in, const int* in_sizes, int n_in,
                              void* d_out, int out_size)
{
    const float* x   = (const float*)d_in[0];
    const float* ctx = (const float*)d_in[1];
    const float* Wq  = (const float*)d_in[2];
    const float* Wk  = (const float*)d_in[3];
    const float* Wv  = (const float*)d_in[4];
    const float* Wo  = (const float*)d_in[5];
    const float* bo  = (const float*)d_in[6];
    const float* g1  = (const float*)d_in[7];
    const float* b1  = (const float*)d_in[8];
    const float* g2  = (const float*)d_in[9];
    const float* b2  = (const float*)d_in[10];
    const float* W1  = (const float*)d_in[11];
    const float* bf1 = (const float*)d_in[12];
    const float* W2  = (const float*)d_in[13];
    const float* bf2 = (const float*)d_in[14];
    float* out = (float*)d_out;

    float* x1 = sym(g_x1);
    __half* nx16 = (__half*)sym(g_nx16);
    __half* nc16 = (__half*)sym(g_nc16);
    __half* h16  = (__half*)sym(g_h16);
    __half* ao16 = (__half*)sym(g_ao16);
    __half* ge16 = (__half*)sym(g_ge16);
    __half* q16  = (__half*)sym(g_q16);
    __half* k16  = (__half*)sym(g_k16);
    __half* v16  = (__half*)sym(g_v16);
    __half* wq16 = (__half*)sym(g_wq16);
    __half* wk16 = (__half*)sym(g_wk16);
    __half* wv16 = (__half*)sym(g_wv16);
    __half* wo16 = (__half*)sym(g_wo16);
    __half* w116 = (__half*)sym(g_w116);
    __half* w216 = (__half*)sym(g_w216);

    cudaFuncSetAttribute(fa_kernel, cudaFuncAttributeMaxDynamicSharedMemorySize, FA_SMEM);
    cudaFuncSetAttribute(qkv_gemm, cudaFuncAttributeMaxDynamicSharedMemorySize, HG_SMEM);
    cudaFuncSetAttribute(hgemm64, cudaFuncAttributeMaxDynamicSharedMemorySize, H64_SMEM);
    cudaFuncSetAttribute(hgemm<2>, cudaFuncAttributeMaxDynamicSharedMemorySize, HG_SMEM);

    // weight transpose + fp16 convert (all 6 in one launch)
    wconv_all<<<WC_BLOCKS, dim3(32, 8)>>>(Wq, Wk, Wv, Wo, W1, W2,
                                          wq16, wk16, wv16, wo16, w116, w216);

    // norm1 for x and ctx in one launch
    ln_dual_kernel<<<2 * ROWS, 256>>>(x, ctx, g1, b1, nx16, nc16);

    // QKV projections fused -> fp16 (z: 0=Q scaled, 1=K, 2=V)
    qkv_gemm<<<dim3(INNER/128, ROWS/128, 3), 256, HG_SMEM>>>(nx16, nc16,
                                                             wq16, wk16, wv16,
                                                             q16, k16, v16);

    // fp16 HMMA flash attention -> fp16
    fa_kernel<<<dim3(SEQ/128, HEADS, BB), 256, FA_SMEM>>>(q16, k16, v16, ao16);

    // out projection + bo + residual(x) -> x1 (fp32, 64-row tiles: 768 CTAs)
    hgemm64<<<dim3(DIMX/128, ROWS/64), 256, H64_SMEM>>>(ao16, wo16, bo, x, x1, DIMX, INNER);

    // norm2 -> fp16
    ln16_kernel<<<ROWS, 256>>>(x1, g2, b2, h16);

    // FFN1 + bias + gelu -> fp16
    hgemm<2><<<dim3(FFN/128, ROWS/128), 256, HG_SMEM>>>(h16, w116, bf1, nullptr, ge16, FFN, DIMX, 1.0f);

    // FFN2 + bias + residual(x1) -> out (fp32, 64-row tiles: 768 CTAs)
    hgemm64<<<dim3(DIMX/128, ROWS/64), 256, H64_SMEM>>>(ge16, w216, bf2, x1, out, DIMX, FFN);
}

// round 17
// speedup vs baseline: 1.1179x; 1.1179x over previous
#include <cuda_runtime.h>
#include <cuda_bf16.h>
#include <cuda_fp16.h>
#include <math.h>
#include <stdint.h>

// ---------------- problem constants ----------------
#define BB     4
#define SEQ    2048
#define DIMX   768
#define HEADS  8
#define HD     64
#define INNER  512
#define FFN    3072
#define ROWS   (BB*SEQ)      // 8192

// ---------------- scratch (device globals) ----------------
__device__ float g_x1[ROWS*DIMX];

__device__ __half g_nx16[ROWS*DIMX];
__device__ __half g_nc16[ROWS*DIMX];
__device__ __half g_h16 [ROWS*DIMX];
__device__ __half g_ao16[ROWS*INNER];
__device__ __half g_ge16[ROWS*FFN];

__device__ __half g_q16[ROWS*INNER];
__device__ __half g_k16[ROWS*INNER];
__device__ __half g_v16[ROWS*INNER];

__device__ __half g_wq16[INNER*DIMX];
__device__ __half g_wk16[INNER*DIMX];
__device__ __half g_wv16[INNER*DIMX];
__device__ __half g_wo16[DIMX*INNER];
__device__ __half g_w116[FFN*DIMX];
__device__ __half g_w216[DIMX*FFN];

// ---------------- PTX helpers (base-target safe: sm_80+) ----------------
__device__ __forceinline__ uint32_t smem_u32(const void* p)
{
    return (uint32_t)__cvta_generic_to_shared(p);
}
__device__ __forceinline__ void cp16(uint32_t dst, const void* src)
{
    asm volatile("cp.async.cg.shared.global [%0], [%1], 16;\n" :: "r"(dst), "l"(src));
}
__device__ __forceinline__ void cp_commit()
{
    asm volatile("cp.async.commit_group;\n" ::: "memory");
}
template <int N>
__device__ __forceinline__ void cp_wait()
{
    asm volatile("cp.async.wait_group %0;\n" :: "n"(N) : "memory");
}
__device__ __forceinline__ void ldsm4(uint32_t* r, uint32_t addr)
{
    asm volatile("ldmatrix.sync.aligned.m8n8.x4.shared.b16 {%0,%1,%2,%3}, [%4];"
                 : "=r"(r[0]), "=r"(r[1]), "=r"(r[2]), "=r"(r[3]) : "r"(addr));
}
__device__ __forceinline__ void ldsm4t(uint32_t* r, uint32_t addr)
{
    asm volatile("ldmatrix.sync.aligned.m8n8.x4.trans.shared.b16 {%0,%1,%2,%3}, [%4];"
                 : "=r"(r[0]), "=r"(r[1]), "=r"(r[2]), "=r"(r[3]) : "r"(addr));
}
__device__ __forceinline__ void mma16816h(float* d, const uint32_t* a, const uint32_t* b)
{
    asm volatile("mma.sync.aligned.m16n8k16.row.col.f32.f16.f16.f32 "
                 "{%0,%1,%2,%3}, {%4,%5,%6,%7}, {%8,%9}, {%0,%1,%2,%3};\n"
                 : "+f"(d[0]), "+f"(d[1]), "+f"(d[2]), "+f"(d[3])
                 : "r"(a[0]), "r"(a[1]), "r"(a[2]), "r"(a[3]), "r"(b[0]), "r"(b[1]));
}
__device__ __forceinline__ float ex2(float x)
{
    float y;
    asm("ex2.approx.f32 %0, %1;" : "=f"(y) : "f"(x));
    return y;
}
__device__ __forceinline__ uint32_t pack_h2(float a, float b)
{
    __half2 t = __floats2half2_rn(a, b);
    return *(uint32_t*)&t;
}

// ---------------- LayerNorm body (-> fp16) ----------------
__device__ __forceinline__ void ln_body(const float* __restrict__ in,
                                        const float* __restrict__ gamma,
                                        const float* __restrict__ beta,
                                        __half* __restrict__ o16,
                                        int row)
{
    const int t = threadIdx.x;
    const float* p = in + (size_t)row * DIMX;

    float v0 = p[t], v1 = p[t + 256], v2 = p[t + 512];
    float s  = v0 + v1 + v2;
    float s2 = v0*v0 + v1*v1 + v2*v2;
    #pragma unroll
    for (int o = 16; o > 0; o >>= 1) {
        s  += __shfl_xor_sync(0xFFFFFFFFu, s,  o);
        s2 += __shfl_xor_sync(0xFFFFFFFFu, s2, o);
    }
    __shared__ float ws[8], ws2[8];
    const int w = t >> 5, ln = t & 31;
    if (ln == 0) { ws[w] = s; ws2[w] = s2; }
    __syncthreads();
    s = 0.f; s2 = 0.f;
    #pragma unroll
    for (int i = 0; i < 8; i++) { s += ws[i]; s2 += ws2[i]; }

    const float mu  = s  * (1.f / DIMX);
    const float var = s2 * (1.f / DIMX) - mu * mu;
    const float inv = rsqrtf(var + 1e-5f);

    const size_t base = (size_t)row * DIMX;
    #pragma unroll
    for (int i = 0; i < 3; i++) {
        const int c = t + i * 256;
        const float vv = (i == 0 ? v0 : i == 1 ? v1 : v2);
        const float y = (vv - mu) * inv * gamma[c] + beta[c];
        o16[base + c] = __float2half_rn(y);
    }
}

__global__ void __launch_bounds__(256) ln16_kernel(const float* __restrict__ in,
                                                   const float* __restrict__ gamma,
                                                   const float* __restrict__ beta,
                                                   __half* __restrict__ o16)
{
    ln_body(in, gamma, beta, o16, blockIdx.x);
}

// ---------------- weight transpose body (fp16 convert) ----------------
__device__ __forceinline__ void wconv_body(const float* __restrict__ W,
                                           __half* __restrict__ T16,
                                           int K, int N, int bx, int by,
                                           int tx, int ty)
{
    __shared__ float tile[32][33];
    const int n0 = bx * 32, k0 = by * 32;
    #pragma unroll
    for (int i = 0; i < 4; i++)
        tile[ty + 8 * i][tx] = W[(size_t)(k0 + ty + 8 * i) * N + n0 + tx];
    __syncthreads();
    #pragma unroll
    for (int i = 0; i < 4; i++) {
        const float v = tile[tx][ty + 8 * i];
        const size_t idx = (size_t)(n0 + ty + 8 * i) * K + k0 + tx;
        T16[idx] = __float2half_rn(v);
    }
}

// ---------------- fused prep: all 6 weight converts + norm1(x, ctx), one launch ----------------
// blocks [0,6144): wconv; [6144, 6144+16384): LayerNorm rows
#define WC_BLOCKS 6144
#define PREP_BLOCKS (WC_BLOCKS + 2 * ROWS)

__global__ void __launch_bounds__(256) prep_kernel(const float* Wq, const float* Wk, const float* Wv,
                                                   const float* Wo, const float* W1, const float* W2,
                                                   __half* wq16, __half* wk16, __half* wv16,
                                                   __half* wo16, __half* w116, __half* w216,
                                                   const float* x, const float* ctx,
                                                   const float* g1, const float* b1,
                                                   __half* nx16, __half* nc16)
{
    const int id = blockIdx.x;
    if (id < WC_BLOCKS) {
        const int tx = threadIdx.x & 31, ty = threadIdx.x >> 5;
        if (id < 384) {
            wconv_body(Wq, wq16, DIMX, INNER, id % 16, id / 16, tx, ty);
        } else if (id < 768) {
            const int l = id - 384;
            wconv_body(Wk, wk16, DIMX, INNER, l % 16, l / 16, tx, ty);
        } else if (id < 1152) {
            const int l = id - 768;
            wconv_body(Wv, wv16, DIMX, INNER, l % 16, l / 16, tx, ty);
        } else if (id < 1536) {
            const int l = id - 1152;
            wconv_body(Wo, wo16, INNER, DIMX, l % 24, l / 24, tx, ty);
        } else if (id < 3840) {
            const int l = id - 1536;
            wconv_body(W1, w116, DIMX, FFN, l % 96, l / 96, tx, ty);
        } else {
            const int l = id - 3840;
            wconv_body(W2, w216, FFN, DIMX, l % 24, l / 24, tx, ty);
        }
    } else {
        const int r = id - WC_BLOCKS;
        if (r < ROWS) ln_body(x, g1, b1, nx16, r);
        else          ln_body(ctx, g1, b1, nc16, r - ROWS);
    }
}

// ---------------- fp16 1-pass HMMA GEMM, 128x128 tile, 3-stage pipeline ----------------
// MODE 1: Cf = D + bias + res                (fp32 out)
// MODE 2: C16 = fp16(gelu(D + bias))
// MODE 4: C16 = fp16(D * oscale)
#define HG_STRIDE 40
#define HG_B (128 * HG_STRIDE)                     // elem offset of B region
#define HG_STAGE_BYTES (2 * 128 * HG_STRIDE * 2)   // 20480
#define HG_SMEM (3 * HG_STAGE_BYTES)               // 61440

template <int MODE>
__device__ __forceinline__ void hgemm_body(const __half* __restrict__ A,
                                           const __half* __restrict__ B,
                                           const float* __restrict__ bias,
                                           const float* __restrict__ res,
                                           float* __restrict__ Cf,
                                           __half* __restrict__ C16,
                                           int N, int K, float oscale,
                                           int bx, int by)
{
    extern __shared__ char dsm[];
    const uint32_t sb = smem_u32(dsm);

    const int t    = threadIdx.x;
    const int lane = t & 31;
    const int wid  = t >> 5;
    const int wm   = wid >> 2;
    const int wn   = wid & 3;

    const int row0 = by * 128;
    const int col0 = bx * 128;
    const int NC = K >> 5;              // chunks of 32

    const int grow = t >> 1;
    const int ghalf = t & 1;
    const uint32_t sm_off = (uint32_t)(grow * HG_STRIDE) * 2 + (uint32_t)ghalf * 32;

    const int a_row = wm * 64 + (lane & 7) + ((lane >> 3) & 1) * 8;
    const int a_col = (lane >> 4) * 8;
    const int b_row = wn * 32 + (lane & 7) + (lane >> 4) * 8;
    const int b_col = ((lane >> 3) & 1) * 8;

    float acc[4][4][4];
    #pragma unroll
    for (int mt = 0; mt < 4; mt++)
        #pragma unroll
        for (int nt = 0; nt < 4; nt++)
            #pragma unroll
            for (int rr = 0; rr < 4; rr++) acc[mt][nt][rr] = 0.f;

    // prologue: issue chunks 0 and 1 as separate groups
    #pragma unroll
    for (int pc = 0; pc < 2; pc++) {
        const uint32_t sp = sb + (uint32_t)pc * HG_STAGE_BYTES;
        const size_t ga = (size_t)(row0 + grow) * K + pc * 32 + ghalf * 16;
        const size_t gb = (size_t)(col0 + grow) * K + pc * 32 + ghalf * 16;
        cp16(sp + sm_off,                  A + ga);
        cp16(sp + sm_off + 16,             A + ga + 8);
        cp16(sp + 2*HG_B + sm_off,         B + gb);
        cp16(sp + 2*HG_B + sm_off + 16,    B + gb + 8);
        cp_commit();
    }

    for (int c = 0; c < NC; c++) {
        const uint32_t st = sb + (uint32_t)(c % 3) * HG_STAGE_BYTES;

        cp_wait<1>();        // chunk c landed (chunk c+1 may be in flight)
        __syncthreads();

        if (c + 2 < NC) {
            const uint32_t sn = sb + (uint32_t)((c + 2) % 3) * HG_STAGE_BYTES;
            const size_t ga = (size_t)(row0 + grow) * K + (c + 2) * 32 + ghalf * 16;
            const size_t gb = (size_t)(col0 + grow) * K + (c + 2) * 32 + ghalf * 16;
            cp16(sn + sm_off,               A + ga);
            cp16(sn + sm_off + 16,          A + ga + 8);
            cp16(sn + 2*HG_B + sm_off,      B + gb);
            cp16(sn + 2*HG_B + sm_off + 16, B + gb + 8);
        }
        cp_commit();         // unconditional: keeps group count exact

        #pragma unroll
        for (int ks = 0; ks < 2; ks++) {
            uint32_t a[4][4], b[4][2];
            #pragma unroll
            for (int mt = 0; mt < 4; mt++) {
                const uint32_t ea = st + 2u * (uint32_t)((a_row + mt * 16) * HG_STRIDE + a_col + ks * 16);
                ldsm4(a[mt], ea);
            }
            #pragma unroll
            for (int p = 0; p < 2; p++) {
                const uint32_t eb = st + 2u * (uint32_t)(HG_B + (b_row + p * 16) * HG_STRIDE + b_col + ks * 16);
                uint32_t r[4];
                ldsm4(r, eb);
                b[2*p][0] = r[0]; b[2*p][1] = r[1]; b[2*p+1][0] = r[2]; b[2*p+1][1] = r[3];
            }
            #pragma unroll
            for (int mt = 0; mt < 4; mt++)
                #pragma unroll
                for (int nt = 0; nt < 4; nt++)
                    mma16816h(acc[mt][nt], a[mt], b[nt]);
        }
    }

    const int gid = lane >> 2, tig = lane & 3;
    #pragma unroll
    for (int mt = 0; mt < 4; mt++) {
        #pragma unroll
        for (int nt = 0; nt < 4; nt++) {
            const int col = col0 + wn * 32 + nt * 8 + tig * 2;
            #pragma unroll
            for (int half = 0; half < 2; half++) {
                const int row = row0 + wm * 64 + mt * 16 + gid + half * 8;
                const size_t idx = (size_t)row * N + col;
                float o0 = acc[mt][nt][half * 2 + 0];
                float o1 = acc[mt][nt][half * 2 + 1];
                if (MODE == 1) {
                    const float2 b2 = *(const float2*)(bias + col);
                    const float2 r2 = *(const float2*)(res + idx);
                    float2 w2;
                    w2.x = o0 + b2.x + r2.x;
                    w2.y = o1 + b2.y + r2.y;
                    *(float2*)(Cf + idx) = w2;
                } else if (MODE == 2) {
                    const float2 b2 = *(const float2*)(bias + col);
                    const float v0 = o0 + b2.x;
                    const float v1 = o1 + b2.y;
                    const float gl0 = 0.5f * v0 * (1.0f + erff(v0 * 0.70710678118654752f));
                    const float gl1 = 0.5f * v1 * (1.0f + erff(v1 * 0.70710678118654752f));
                    *(__half2*)(C16 + idx) = __floats2half2_rn(gl0, gl1);
                } else {
                    *(__half2*)(C16 + idx) = __floats2half2_rn(o0 * oscale, o1 * oscale);
                }
            }
        }
    }
}

template <int MODE>
__global__ void __launch_bounds__(256, 2) hgemm(const __half* __restrict__ A,
                                                const __half* __restrict__ B,
                                                const float* __restrict__ bias,
                                                const float* __restrict__ res,
                                                float* __restrict__ Cf,
                                                __half* __restrict__ C16,
                                                int N, int K, float oscale)
{
    hgemm_body<MODE>(A, B, bias, res, Cf, C16, N, K, oscale, blockIdx.x, blockIdx.y);
}

// fused QKV -> fp16: z=0 Q (A=nx, scaled by 0.125*log2e), z=1 K, z=2 V (A=nc)
__global__ void __launch_bounds__(256, 2) qkv_gemm(const __half* nx16, const __half* nc16,
                                                   const __half* wq16, const __half* wk16,
                                                   const __half* wv16,
                                                   __half* q16, __half* k16, __half* v16)
{
    const int z = blockIdx.z;
    const __half* A = (z == 0) ? nx16 : nc16;
    const __half* B = (z == 0) ? wq16 : (z == 1) ? wk16 : wv16;
    __half* C = (z == 0) ? q16 : (z == 1) ? k16 : v16;
    const float osc = (z == 0) ? (0.125f * 1.44269504f) : 1.0f;
    hgemm_body<4>(A, B, nullptr, nullptr, nullptr, C, INNER, DIMX, osc, blockIdx.x, blockIdx.y);
}

// ---------------- fp16 HMMA flash attention (1-pass, no-max softmax, 3-stage) ----------------
// CTA: 128 q-rows x head (dim 64). 8 warps, each m16. K/V chunks of 64 keys.
#define KST 72
#define KTILE_B (64 * KST * 2)      // 9216
#define STAGE_B (2 * KTILE_B)       // 18432: K,V
#define FA_SMEM (3 * STAGE_B)       // 55296

__device__ __forceinline__ void fa_load_chunk(uint32_t st, int arr, int rr, int hf,
                                              const __half* kb, const __half* vb, int m0)
{
    const __half* gb = arr ? vb : kb;
    const uint32_t dst = st + (uint32_t)arr * KTILE_B + (uint32_t)(rr * KST + hf * 32) * 2;
    const __half* src = gb + (size_t)(m0 + rr) * INNER + hf * 32;
    #pragma unroll
    for (int j = 0; j < 4; j++)
        cp16(dst + j * 16, src + j * 8);
}

__global__ void __launch_bounds__(256, 2) fa_kernel(const __half* __restrict__ q16,
                                                    const __half* __restrict__ k16,
                                                    const __half* __restrict__ v16,
                                                    __half* __restrict__ ao16)
{
    extern __shared__ char fsm[];
    const uint32_t sb = smem_u32(fsm);

    const int n0 = blockIdx.x * 128;
    const int h  = blockIdx.y;
    const int b  = blockIdx.z;
    const int t  = threadIdx.x;
    const int lane = t & 31;
    const int w  = t >> 5;
    const int gid = lane >> 2, tig = lane & 3;

    // ---- stage Q (128 x 64 fp16) into stage-0 region, ldmatrix to regs ----
    {
        const int qrow = t >> 1, qhf = t & 1;
        const __half* qb = q16 + (size_t)(b * SEQ + n0 + qrow) * INNER + h * HD + qhf * 32;
        const uint32_t dst = sb + (uint32_t)(qrow * KST + qhf * 32) * 2;
        #pragma unroll
        for (int j = 0; j < 4; j++)
            cp16(dst + j * 16, qb + j * 8);
        cp_commit();
        cp_wait<0>();
        __syncthreads();
    }

    uint32_t qf[4][4];
    {
        const int a_row = w * 16 + (lane & 7) + ((lane >> 3) & 1) * 8;
        const int a_col = (lane >> 4) * 8;
        #pragma unroll
        for (int kt = 0; kt < 4; kt++) {
            const uint32_t ea = sb + 2u * (uint32_t)(a_row * KST + kt * 16 + a_col);
            ldsm4(qf[kt], ea);
        }
    }
    __syncthreads();   // everyone done reading Q staging before K/V overwrite

    float lr0 = 0.f, lr1 = 0.f;
    float o[8][4];
    #pragma unroll
    for (int nt = 0; nt < 8; nt++)
        #pragma unroll
        for (int rr = 0; rr < 4; rr++) o[nt][rr] = 0.f;

    const __half* kbase = k16 + (size_t)(b * SEQ) * INNER + h * HD;
    const __half* vbase = v16 + (size_t)(b * SEQ) * INNER + h * HD;

    const int arr = t >> 7;
    const int rem = t & 127;
    const int rr_ = rem >> 1;
    const int hf_ = rem & 1;

    const int kb_row = (lane & 7) + (lane >> 4) * 8;       // K as B (non-trans)
    const int kb_col = ((lane >> 3) & 1) * 8;
    const int v_row  = (lane & 7) + ((lane >> 3) & 1) * 8; // V via trans
    const int v_cb   = (lane >> 4) * 8;

    // prologue: issue chunks 0 and 1 as separate groups
    fa_load_chunk(sb,           arr, rr_, hf_, kbase, vbase, 0);
    cp_commit();
    fa_load_chunk(sb + STAGE_B, arr, rr_, hf_, kbase, vbase, 64);
    cp_commit();

    const int NCH = SEQ / 64;
    for (int c = 0; c < NCH; c++) {
        const uint32_t st = sb + (uint32_t)(c % 3) * STAGE_B;

        cp_wait<1>();      // chunk c landed; chunk c+1 may still fly
        __syncthreads();

        if (c + 2 < NCH) {
            fa_load_chunk(sb + (uint32_t)((c + 2) % 3) * STAGE_B, arr, rr_, hf_,
                          kbase, vbase, (c + 2) * 64);
        }
        cp_commit();       // unconditional: keeps group count exact

        // ---- S = Q K^T; scores include scale*log2(e) ----
        float s[8][4];
        #pragma unroll
        for (int nt = 0; nt < 8; nt++)
            #pragma unroll
            for (int rr = 0; rr < 4; rr++) s[nt][rr] = 0.f;

        #pragma unroll
        for (int kt = 0; kt < 4; kt++) {
            #pragma unroll
            for (int p = 0; p < 4; p++) {
                const uint32_t eb = st + 2u * (uint32_t)((p * 16 + kb_row) * KST + kt * 16 + kb_col);
                uint32_t r[4];
                ldsm4(r, eb);
                mma16816h(s[2*p],   qf[kt], r);
                mma16816h(s[2*p+1], qf[kt], r + 2);
            }
        }

        // ---- no-max softmax: P = 2^s ----
        uint32_t pa[4][4];
        #pragma unroll
        for (int nt = 0; nt < 8; nt++) {
            const float p0 = ex2(s[nt][0]);
            const float p1 = ex2(s[nt][1]);
            const float p2 = ex2(s[nt][2]);
            const float p3 = ex2(s[nt][3]);
            lr0 += p0 + p1;
            lr1 += p2 + p3;
            const int kt = nt >> 1, hf = nt & 1;
            pa[kt][hf * 2 + 0] = pack_h2(p0, p1);
            pa[kt][hf * 2 + 1] = pack_h2(p2, p3);
        }

        // ---- O += P V, V via ldmatrix.trans ----
        #pragma unroll
        for (int kt = 0; kt < 4; kt++) {
            #pragma unroll
            for (int g = 0; g < 4; g++) {
                const uint32_t ev = st + (uint32_t)KTILE_B
                                  + 2u * (uint32_t)((kt * 16 + v_row) * KST + g * 16 + v_cb);
                uint32_t r[4];
                ldsm4t(r, ev);
                mma16816h(o[2*g],   pa[kt], r);
                mma16816h(o[2*g+1], pa[kt], r + 2);
            }
        }
    }

    // ---- deferred row-sum reduction + epilogue -> fp16 ----
    lr0 += __shfl_xor_sync(0xFFFFFFFFu, lr0, 1);
    lr0 += __shfl_xor_sync(0xFFFFFFFFu, lr0, 2);
    lr1 += __shfl_xor_sync(0xFFFFFFFFu, lr1, 1);
    lr1 += __shfl_xor_sync(0xFFFFFFFFu, lr1, 2);
    const float inv0 = 1.f / lr0;
    const float inv1 = 1.f / lr1;
    #pragma unroll
    for (int nt = 0; nt < 8; nt++) {
        const int col = h * HD + nt * 8 + tig * 2;
        #pragma unroll
        for (int half = 0; half < 2; half++) {
            const int row = n0 + w * 16 + gid + half * 8;
            const size_t idx = (size_t)(b * SEQ + row) * INNER + col;
            const float inv = half ? inv1 : inv0;
            *(__half2*)(ao16 + idx) = __floats2half2_rn(o[nt][half * 2 + 0] * inv,
                                                        o[nt][half * 2 + 1] * inv);
        }
    }
}

// ---------------- host launcher ----------------
static float* sym(const void* s)
{
    void* p = nullptr;
    cudaGetSymbolAddress(&p, s);
    return (float*)p;
}

extern "C" void kernel_launch(void* const* d_in, const int* in_sizes, int n_in,
                              void* d_out, int out_size)
{
    const float* x   = (const float*)d_in[0];
    const float* ctx = (const float*)d_in[1];
    const float* Wq  = (const float*)d_in[2];
    const float* Wk  = (const float*)d_in[3];
    const float* Wv  = (const float*)d_in[4];
    const float* Wo  = (const float*)d_in[5];
    const float* bo  = (const float*)d_in[6];
    const float* g1  = (const float*)d_in[7];
    const float* b1  = (const float*)d_in[8];
    const float* g2  = (const float*)d_in[9];
    const float* b2  = (const float*)d_in[10];
    const float* W1  = (const float*)d_in[11];
    const float* bf1 = (const float*)d_in[12];
    const float* W2  = (const float*)d_in[13];
    const float* bf2 = (const float*)d_in[14];
    float* out = (float*)d_out;

    float* x1 = sym(g_x1);
    __half* nx16 = (__half*)sym(g_nx16);
    __half* nc16 = (__half*)sym(g_nc16);
    __half* h16  = (__half*)sym(g_h16);
    __half* ao16 = (__half*)sym(g_ao16);
    __half* ge16 = (__half*)sym(g_ge16);
    __half* q16  = (__half*)sym(g_q16);
    __half* k16  = (__half*)sym(g_k16);
    __half* v16  = (__half*)sym(g_v16);
    __half* wq16 = (__half*)sym(g_wq16);
    __half* wk16 = (__half*)sym(g_wk16);
    __half* wv16 = (__half*)sym(g_wv16);
    __half* wo16 = (__half*)sym(g_wo16);
    __half* w116 = (__half*)sym(g_w116);
    __half* w216 = (__half*)sym(g_w216);

    cudaFuncSetAttribute(fa_kernel, cudaFuncAttributeMaxDynamicSharedMemorySize, FA_SMEM);
    cudaFuncSetAttribute(qkv_gemm, cudaFuncAttributeMaxDynamicSharedMemorySize, HG_SMEM);
    cudaFuncSetAttribute(hgemm<1>, cudaFuncAttributeMaxDynamicSharedMemorySize, HG_SMEM);
    cudaFuncSetAttribute(hgemm<2>, cudaFuncAttributeMaxDynamicSharedMemorySize, HG_SMEM);

    // fused prep: weight transpose/convert + norm1(x, ctx), one launch
    prep_kernel<<<PREP_BLOCKS, 256>>>(Wq, Wk, Wv, Wo, W1, W2,
                                      wq16, wk16, wv16, wo16, w116, w216,
                                      x, ctx, g1, b1, nx16, nc16);

    // QKV projections fused -> fp16 (z: 0=Q scaled, 1=K, 2=V)
    qkv_gemm<<<dim3(INNER/128, ROWS/128, 3), 256, HG_SMEM>>>(nx16, nc16,
                                                             wq16, wk16, wv16,
                                                             q16, k16, v16);

    // fp16 HMMA flash attention -> fp16
    fa_kernel<<<dim3(SEQ/128, HEADS, BB), 256, FA_SMEM>>>(q16, k16, v16, ao16);

    // out projection + bo + residual(x) -> x1 (fp32)
    hgemm<1><<<dim3(DIMX/128, ROWS/128), 256, HG_SMEM>>>(ao16, wo16, bo, x, x1, nullptr, DIMX, INNER, 1.0f);

    // norm2 -> fp16
    ln16_kernel<<<ROWS, 256>>>(x1, g2, b2, h16);

    // FFN1 + bias + gelu -> fp16
    hgemm<2><<<dim3(FFN/128, ROWS/128), 256, HG_SMEM>>>(h16, w116, bf1, nullptr, nullptr, ge16, FFN, DIMX, 1.0f);

    // FFN2 + bias + residual(x1) -> out (fp32)
    hgemm<1><<<dim3(DIMX/128, ROWS/128), 256, HG_SMEM>>>(ge16, w216, bf2, x1, out, nullptr, DIMX, FFN, 1.0f);
}